// round 5
// baseline (speedup 1.0000x reference)
#include <cuda_runtime.h>
#include <cstdint>
#include <cstddef>

#define T_LEN 16384
#define L_LAB 1024
#define LOG2E 1.4426950408889634f
#define LN2_D 0.6931471805599453
#define NBLK  128
#define TPB   256

// ---- persistent state (scratch; no allocations allowed) ----
__device__ unsigned long long g_pub[2][L_LAB];  // {tag<<32 | float_bits}
__device__ double g_csum;
__device__ double g_gold;

static __device__ __forceinline__ float ex2f(float x) {
    float r; asm("ex2.approx.ftz.f32 %0, %1;" : "=f"(r) : "f"(x)); return r;
}
static __device__ __forceinline__ float lg2f_(float x) {
    float r; asm("lg2.approx.f32 %0, %1;" : "=f"(r) : "f"(x)); return r;
}
static __device__ __forceinline__ unsigned long long ld_pub(const unsigned long long* p) {
    unsigned long long v;
    asm volatile("ld.relaxed.gpu.global.b64 %0, [%1];" : "=l"(v) : "l"(p));
    return v;
}
static __device__ __forceinline__ void st_pub(unsigned long long* p, unsigned long long v) {
    asm volatile("st.relaxed.gpu.global.b64 [%0], %1;" :: "l"(p), "l"(v));
}

__global__ void crf_reset() {
    int i = blockIdx.x * blockDim.x + threadIdx.x;
    if (i < 2 * L_LAB) ((unsigned long long*)g_pub)[i] = 0ull;
}

// Main persistent kernel: blocks 0..127 run the forward recurrence (8 label-rows
// per block, one row per warp, W row resident in 32 registers/thread).
// Block 128 computes the gold-path score concurrently.
__global__ void __launch_bounds__(TPB, 1) crf_main(const float* __restrict__ pred,
                                                   const int*   __restrict__ ref,
                                                   const float* __restrict__ trans)
{
    if (blockIdx.x == NBLK) {
        // ---- gold path score (hidden under the main loop) ----
        __shared__ double red[TPB];
        int tid = threadIdx.x;
        double g = 0.0;
        for (int t = tid; t < T_LEN; t += TPB) {
            int r = __ldg(&ref[t]);
            int p = (t == 0) ? (L_LAB - 2) : __ldg(&ref[t - 1]);
            g += (double)__ldg(&pred[(size_t)t * L_LAB + r])
               + (double)__ldg(&trans[(size_t)r * L_LAB + p]);
        }
        red[tid] = g; __syncthreads();
        for (int s = TPB / 2; s > 0; s >>= 1) {
            if (tid < s) red[tid] += red[tid + s];
            __syncthreads();
        }
        if (tid == 0)
            g_gold = red[0] + (double)__ldg(&trans[(size_t)(L_LAB - 1) * L_LAB + __ldg(&ref[T_LEN - 1])]);
        return;
    }

    __shared__ __align__(16) float smA[L_LAB];
    const int tid = threadIdx.x;
    const int w = tid >> 5, l = tid & 31;
    const int j = blockIdx.x * 8 + w;   // this warp's output label row (0..1023)

    // Load W[j,:] * log2e into 32 registers. Element i = k*128 + 4*l + m -> wr[4k+m].
    float wr[32];
    {
        const float* tr = trans + (size_t)j * L_LAB;
        #pragma unroll
        for (int k = 0; k < 8; ++k) {
            float4 v = *reinterpret_cast<const float4*>(tr + k * 128 + 4 * l);
            wr[4 * k + 0] = v.x * LOG2E; wr[4 * k + 1] = v.y * LOG2E;
            wr[4 * k + 2] = v.z * LOG2E; wr[4 * k + 3] = v.w * LOG2E;
        }
    }
    // W[j, START]: i = 1022 -> k=7, lane 31, m=2 -> reg 30
    float wstart = __shfl_sync(0xffffffffu, wr[30], 31);

    // Step 1 closed form: A''(1)[j] = (W[j,START] + pred[0,j]) * log2e
    {
        float a1 = wstart + __ldg(&pred[j]) * LOG2E;
        if (l == 0)
            st_pub(&g_pub[1][j],
                   ((unsigned long long)1u << 32) | (unsigned long long)__float_as_uint(a1));
    }

    double csum = 0.0;
    float fnext = __ldg(&pred[(size_t)L_LAB + j]);   // feats for t=1

    for (int t = 1; t < T_LEN; ++t) {
        // ---- stage alpha(t): each thread owns 4 consecutive labels ----
        {
            unsigned long long* src = g_pub[t & 1];
            const unsigned tag = (unsigned)t;
            int base = tid * 4;
            #pragma unroll
            for (int q = 0; q < 4; ++q) {
                unsigned long long e;
                do { e = ld_pub(src + base + q); } while ((unsigned)(e >> 32) != tag);
                smA[base + q] = __uint_as_float((unsigned)(e & 0xffffffffull));
            }
        }
        __syncthreads();
        float c = smA[0];                 // deterministic per-step normalizer
        if (blockIdx.x == 0 && tid == 0) csum += (double)c;

        float fcur = fnext;
        if (t + 1 < T_LEN) fnext = __ldg(&pred[(size_t)(t + 1) * L_LAB + j]);

        // ---- row j: s = sum_i exp2(A[i] + Wl[j,i]) ----
        float a0 = 0.f, a1 = 0.f, a2 = 0.f, a3 = 0.f;
        #pragma unroll
        for (int k = 0; k < 8; ++k) {
            float4 v = *reinterpret_cast<const float4*>(&smA[k * 128 + 4 * l]);
            a0 += ex2f(v.x + wr[4 * k + 0]);
            a1 += ex2f(v.y + wr[4 * k + 1]);
            a2 += ex2f(v.z + wr[4 * k + 2]);
            a3 += ex2f(v.w + wr[4 * k + 3]);
        }
        float s = (a0 + a1) + (a2 + a3);
        #pragma unroll
        for (int o = 16; o > 0; o >>= 1) s += __shfl_xor_sync(0xffffffffu, s, o);

        if (l == 0) {
            float an = lg2f_(s) - c + fcur * LOG2E;
            st_pub(&g_pub[(t + 1) & 1][j],
                   ((unsigned long long)(unsigned)(t + 1) << 32)
                   | (unsigned long long)__float_as_uint(an));
        }
        __syncthreads();   // protect smA before next stage overwrites it
    }

    if (blockIdx.x == 0 && tid == 0) g_csum = csum;
}

// Terminal: forward = LSE_j(A''(T)[j] + Wl[STOP,j]) + Csum (max-stabilized: the
// STOP row is uniformly -1e4, so without the max everything would underflow).
__global__ void crf_final(const float* __restrict__ trans, float* __restrict__ out)
{
    __shared__ float  sm[TPB];
    __shared__ double sd[TPB];
    int tid = threadIdx.x;

    float x[4];
    float m = -3.4e38f;
    #pragma unroll
    for (int q = 0; q < 4; ++q) {
        int jj = q * TPB + tid;
        float a  = __uint_as_float((unsigned)(g_pub[T_LEN & 1][jj] & 0xffffffffull));
        float wl = __ldg(&trans[(size_t)(L_LAB - 1) * L_LAB + jj]) * LOG2E;
        x[q] = a + wl;
        m = fmaxf(m, x[q]);
    }
    sm[tid] = m; __syncthreads();
    for (int s = TPB / 2; s > 0; s >>= 1) {
        if (tid < s) sm[tid] = fmaxf(sm[tid], sm[tid + s]);
        __syncthreads();
    }
    float M = sm[0];

    double loc = 0.0;
    #pragma unroll
    for (int q = 0; q < 4; ++q) loc += (double)ex2f(x[q] - M);
    sd[tid] = loc; __syncthreads();
    for (int s = TPB / 2; s > 0; s >>= 1) {
        if (tid < s) sd[tid] += sd[tid + s];
        __syncthreads();
    }
    if (tid == 0) {
        double fwd = (log2(sd[0]) + (double)M + g_csum) * LN2_D;
        out[0] = (float)(fwd - g_gold);
    }
}

extern "C" void kernel_launch(void* const* d_in, const int* in_sizes, int n_in,
                              void* d_out, int out_size)
{
    const float* pred = nullptr;
    const int*   ref  = nullptr;
    const float* trans = nullptr;
    for (int i = 0; i < n_in; ++i) {
        if (in_sizes[i] == T_LEN)                 ref   = (const int*)d_in[i];
        else if (in_sizes[i] == L_LAB * L_LAB)    trans = (const float*)d_in[i];
        else if (in_sizes[i] == T_LEN * L_LAB)    pred  = (const float*)d_in[i];
    }
    crf_reset<<<8, 256>>>();
    crf_main<<<NBLK + 1, TPB>>>(pred, ref, trans);
    crf_final<<<1, TPB>>>(trans, (float*)d_out);
}

// round 6
// speedup vs baseline: 1.0108x; 1.0108x over previous
#include <cuda_runtime.h>
#include <cstdint>
#include <cstddef>

#define T_LEN 16384
#define L_LAB 1024
#define LOG2E 1.4426950408889634f
#define LN2_D 0.6931471805599453
#define NBLK  128
#define TPB   256

// ---- persistent state (scratch; no allocations allowed) ----
__device__ unsigned long long g_pub[2][L_LAB];  // {tag<<32 | float_bits}
__device__ double g_csum;
__device__ double g_gold;

static __device__ __forceinline__ float ex2f(float x) {
    float r; asm("ex2.approx.ftz.f32 %0, %1;" : "=f"(r) : "f"(x)); return r;
}
static __device__ __forceinline__ float lg2f_(float x) {
    float r; asm("lg2.approx.f32 %0, %1;" : "=f"(r) : "f"(x)); return r;
}
static __device__ __forceinline__ unsigned long long ld_pub(const unsigned long long* p) {
    unsigned long long v;
    asm volatile("ld.relaxed.gpu.global.b64 %0, [%1];" : "=l"(v) : "l"(p));
    return v;
}
static __device__ __forceinline__ void st_pub(unsigned long long* p, unsigned long long v) {
    asm volatile("st.relaxed.gpu.global.b64 [%0], %1;" :: "l"(p), "l"(v));
}

__global__ void crf_reset() {
    int i = blockIdx.x * blockDim.x + threadIdx.x;
    if (i < 2 * L_LAB) ((unsigned long long*)g_pub)[i] = 0ull;
}

// Main persistent kernel: blocks 0..127 run the forward recurrence (8 label-rows
// per block, one row per warp, W row resident in 32 registers/thread).
// Block 128 computes the gold-path score concurrently.
__global__ void __launch_bounds__(TPB, 1) crf_main(const float* __restrict__ pred,
                                                   const int*   __restrict__ ref,
                                                   const float* __restrict__ trans)
{
    if (blockIdx.x == NBLK) {
        // ---- gold path score (hidden under the main loop) ----
        __shared__ double red[TPB];
        int tid = threadIdx.x;
        double g = 0.0;
        for (int t = tid; t < T_LEN; t += TPB) {
            int r = __ldg(&ref[t]);
            int p = (t == 0) ? (L_LAB - 2) : __ldg(&ref[t - 1]);
            g += (double)__ldg(&pred[(size_t)t * L_LAB + r])
               + (double)__ldg(&trans[(size_t)r * L_LAB + p]);
        }
        red[tid] = g; __syncthreads();
        for (int s = TPB / 2; s > 0; s >>= 1) {
            if (tid < s) red[tid] += red[tid + s];
            __syncthreads();
        }
        if (tid == 0)
            g_gold = red[0] + (double)__ldg(&trans[(size_t)(L_LAB - 1) * L_LAB + __ldg(&ref[T_LEN - 1])]);
        return;
    }

    __shared__ __align__(16) float smA[L_LAB];
    const int tid = threadIdx.x;
    const int w = tid >> 5, l = tid & 31;
    const int j = blockIdx.x * 8 + w;   // this warp's output label row (0..1023)

    // Load W[j,:] * log2e into 32 registers. Element i = k*128 + 4*l + m -> wr[4k+m].
    float wr[32];
    {
        const float* tr = trans + (size_t)j * L_LAB;
        #pragma unroll
        for (int k = 0; k < 8; ++k) {
            float4 v = *reinterpret_cast<const float4*>(tr + k * 128 + 4 * l);
            wr[4 * k + 0] = v.x * LOG2E; wr[4 * k + 1] = v.y * LOG2E;
            wr[4 * k + 2] = v.z * LOG2E; wr[4 * k + 3] = v.w * LOG2E;
        }
    }
    // W[j, START]: i = 1022 -> k=7, lane 31, m=2 -> reg 30
    float wstart = __shfl_sync(0xffffffffu, wr[30], 31);

    // Step 1 closed form: A''(1)[j] = (W[j,START] + pred[0,j]) * log2e
    {
        float a1 = wstart + __ldg(&pred[j]) * LOG2E;
        if (l == 0)
            st_pub(&g_pub[1][j],
                   ((unsigned long long)1u << 32) | (unsigned long long)__float_as_uint(a1));
    }

    double csum = 0.0;
    float fnext = __ldg(&pred[(size_t)L_LAB + j]);   // feats for t=1

    for (int t = 1; t < T_LEN; ++t) {
        // ---- stage alpha(t): each thread owns 4 consecutive labels ----
        {
            unsigned long long* src = g_pub[t & 1];
            const unsigned tag = (unsigned)t;
            int base = tid * 4;
            #pragma unroll
            for (int q = 0; q < 4; ++q) {
                unsigned long long e;
                do { e = ld_pub(src + base + q); } while ((unsigned)(e >> 32) != tag);
                smA[base + q] = __uint_as_float((unsigned)(e & 0xffffffffull));
            }
        }
        __syncthreads();
        float c = smA[0];                 // deterministic per-step normalizer
        if (blockIdx.x == 0 && tid == 0) csum += (double)c;

        float fcur = fnext;
        if (t + 1 < T_LEN) fnext = __ldg(&pred[(size_t)(t + 1) * L_LAB + j]);

        // ---- row j: s = sum_i exp2(A[i] + Wl[j,i]) ----
        float a0 = 0.f, a1 = 0.f, a2 = 0.f, a3 = 0.f;
        #pragma unroll
        for (int k = 0; k < 8; ++k) {
            float4 v = *reinterpret_cast<const float4*>(&smA[k * 128 + 4 * l]);
            a0 += ex2f(v.x + wr[4 * k + 0]);
            a1 += ex2f(v.y + wr[4 * k + 1]);
            a2 += ex2f(v.z + wr[4 * k + 2]);
            a3 += ex2f(v.w + wr[4 * k + 3]);
        }
        float s = (a0 + a1) + (a2 + a3);
        #pragma unroll
        for (int o = 16; o > 0; o >>= 1) s += __shfl_xor_sync(0xffffffffu, s, o);

        if (l == 0) {
            float an = lg2f_(s) - c + fcur * LOG2E;
            st_pub(&g_pub[(t + 1) & 1][j],
                   ((unsigned long long)(unsigned)(t + 1) << 32)
                   | (unsigned long long)__float_as_uint(an));
        }
        __syncthreads();   // protect smA before next stage overwrites it
    }

    if (blockIdx.x == 0 && tid == 0) g_csum = csum;
}

// Terminal: forward = LSE_j(A''(T)[j] + Wl[STOP,j]) + Csum (max-stabilized: the
// STOP row is uniformly -1e4, so without the max everything would underflow).
__global__ void crf_final(const float* __restrict__ trans, float* __restrict__ out)
{
    __shared__ float  sm[TPB];
    __shared__ double sd[TPB];
    int tid = threadIdx.x;

    float x[4];
    float m = -3.4e38f;
    #pragma unroll
    for (int q = 0; q < 4; ++q) {
        int jj = q * TPB + tid;
        float a  = __uint_as_float((unsigned)(g_pub[T_LEN & 1][jj] & 0xffffffffull));
        float wl = __ldg(&trans[(size_t)(L_LAB - 1) * L_LAB + jj]) * LOG2E;
        x[q] = a + wl;
        m = fmaxf(m, x[q]);
    }
    sm[tid] = m; __syncthreads();
    for (int s = TPB / 2; s > 0; s >>= 1) {
        if (tid < s) sm[tid] = fmaxf(sm[tid], sm[tid + s]);
        __syncthreads();
    }
    float M = sm[0];

    double loc = 0.0;
    #pragma unroll
    for (int q = 0; q < 4; ++q) loc += (double)ex2f(x[q] - M);
    sd[tid] = loc; __syncthreads();
    for (int s = TPB / 2; s > 0; s >>= 1) {
        if (tid < s) sd[tid] += sd[tid + s];
        __syncthreads();
    }
    if (tid == 0) {
        double fwd = (log2(sd[0]) + (double)M + g_csum) * LN2_D;
        out[0] = (float)(fwd - g_gold);
    }
}

extern "C" void kernel_launch(void* const* d_in, const int* in_sizes, int n_in,
                              void* d_out, int out_size)
{
    const float* pred = nullptr;
    const int*   ref  = nullptr;
    const float* trans = nullptr;
    for (int i = 0; i < n_in; ++i) {
        if (in_sizes[i] == T_LEN)                 ref   = (const int*)d_in[i];
        else if (in_sizes[i] == L_LAB * L_LAB)    trans = (const float*)d_in[i];
        else if (in_sizes[i] == T_LEN * L_LAB)    pred  = (const float*)d_in[i];
    }
    crf_reset<<<8, 256>>>();
    crf_main<<<NBLK + 1, TPB>>>(pred, ref, trans);
    crf_final<<<1, TPB>>>(trans, (float*)d_out);
}

// round 7
// speedup vs baseline: 1.3682x; 1.3536x over previous
#include <cuda_runtime.h>
#include <cstdint>
#include <cstddef>

#define T_LEN 16384
#define L_LAB 1024
#define LOG2E 1.4426950408889634f
#define LN2_D 0.6931471805599453
#define NBLK  128
#define TPB   256

// ---- persistent state (scratch; no allocations allowed) ----
__device__ unsigned long long g_pub[2][L_LAB];  // {tag<<32 | float_bits}
__device__ double g_csum;
__device__ double g_gold;

static __device__ __forceinline__ float ex2f(float x) {
    float r; asm("ex2.approx.ftz.f32 %0, %1;" : "=f"(r) : "f"(x)); return r;
}
static __device__ __forceinline__ float lg2f_(float x) {
    float r; asm("lg2.approx.f32 %0, %1;" : "=f"(r) : "f"(x)); return r;
}
static __device__ __forceinline__ unsigned long long ld_pub(const unsigned long long* p) {
    unsigned long long v;
    asm volatile("ld.relaxed.gpu.global.b64 %0, [%1];" : "=l"(v) : "l"(p));
    return v;
}
static __device__ __forceinline__ void st_pub(unsigned long long* p, unsigned long long v) {
    asm volatile("st.relaxed.gpu.global.b64 [%0], %1;" :: "l"(p), "l"(v));
}

__global__ void crf_reset() {
    int i = blockIdx.x * blockDim.x + threadIdx.x;
    if (i < 2 * L_LAB) ((unsigned long long*)g_pub)[i] = 0ull;
}

// Main persistent kernel: blocks 0..127 run the forward recurrence (8 label-rows
// per block, one row per warp, W row resident in 32 registers/thread).
// Block 128 computes the gold-path score concurrently.
__global__ void __launch_bounds__(TPB, 1) crf_main(const float* __restrict__ pred,
                                                   const int*   __restrict__ ref,
                                                   const float* __restrict__ trans)
{
    if (blockIdx.x == NBLK) {
        // ---- gold path score (hidden under the main loop) ----
        __shared__ double red[TPB];
        int tid = threadIdx.x;
        double g = 0.0;
        for (int t = tid; t < T_LEN; t += TPB) {
            int r = __ldg(&ref[t]);
            int p = (t == 0) ? (L_LAB - 2) : __ldg(&ref[t - 1]);
            g += (double)__ldg(&pred[(size_t)t * L_LAB + r])
               + (double)__ldg(&trans[(size_t)r * L_LAB + p]);
        }
        red[tid] = g; __syncthreads();
        for (int s = TPB / 2; s > 0; s >>= 1) {
            if (tid < s) red[tid] += red[tid + s];
            __syncthreads();
        }
        if (tid == 0)
            g_gold = red[0] + (double)__ldg(&trans[(size_t)(L_LAB - 1) * L_LAB + __ldg(&ref[T_LEN - 1])]);
        return;
    }

    __shared__ __align__(16) float smA[L_LAB];
    const int tid = threadIdx.x;
    const int w = tid >> 5, l = tid & 31;
    const int j = blockIdx.x * 8 + w;   // this warp's output label row (0..1023)

    // Load W[j,:] * log2e into 32 registers. Element i = k*128 + 4*l + m -> wr[4k+m].
    float wr[32];
    {
        const float* tr = trans + (size_t)j * L_LAB;
        #pragma unroll
        for (int k = 0; k < 8; ++k) {
            float4 v = *reinterpret_cast<const float4*>(tr + k * 128 + 4 * l);
            wr[4 * k + 0] = v.x * LOG2E; wr[4 * k + 1] = v.y * LOG2E;
            wr[4 * k + 2] = v.z * LOG2E; wr[4 * k + 3] = v.w * LOG2E;
        }
    }
    // W[j, START]: i = 1022 -> k=7, lane 31, m=2 -> reg 30
    float wstart = __shfl_sync(0xffffffffu, wr[30], 31);

    // Step 1 closed form: A''(1)[j] = (W[j,START] + pred[0,j]) * log2e
    {
        float a1 = wstart + __ldg(&pred[j]) * LOG2E;
        if (l == 0)
            st_pub(&g_pub[1][j],
                   ((unsigned long long)1u << 32) | (unsigned long long)__float_as_uint(a1));
    }

    double csum = 0.0;
    float fnext = __ldg(&pred[(size_t)L_LAB + j]);   // feats for t=1

    for (int t = 1; t < T_LEN; ++t) {
        // ---- stage alpha(t): each thread owns 4 consecutive labels ----
        {
            unsigned long long* src = g_pub[t & 1];
            const unsigned tag = (unsigned)t;
            int base = tid * 4;
            #pragma unroll
            for (int q = 0; q < 4; ++q) {
                unsigned long long e;
                do { e = ld_pub(src + base + q); } while ((unsigned)(e >> 32) != tag);
                smA[base + q] = __uint_as_float((unsigned)(e & 0xffffffffull));
            }
        }
        __syncthreads();
        float c = smA[0];                 // deterministic per-step normalizer
        if (blockIdx.x == 0 && tid == 0) csum += (double)c;

        float fcur = fnext;
        if (t + 1 < T_LEN) fnext = __ldg(&pred[(size_t)(t + 1) * L_LAB + j]);

        // ---- row j: s = sum_i exp2(A[i] + Wl[j,i]) ----
        float a0 = 0.f, a1 = 0.f, a2 = 0.f, a3 = 0.f;
        #pragma unroll
        for (int k = 0; k < 8; ++k) {
            float4 v = *reinterpret_cast<const float4*>(&smA[k * 128 + 4 * l]);
            a0 += ex2f(v.x + wr[4 * k + 0]);
            a1 += ex2f(v.y + wr[4 * k + 1]);
            a2 += ex2f(v.z + wr[4 * k + 2]);
            a3 += ex2f(v.w + wr[4 * k + 3]);
        }
        float s = (a0 + a1) + (a2 + a3);
        #pragma unroll
        for (int o = 16; o > 0; o >>= 1) s += __shfl_xor_sync(0xffffffffu, s, o);

        if (l == 0) {
            float an = lg2f_(s) - c + fcur * LOG2E;
            st_pub(&g_pub[(t + 1) & 1][j],
                   ((unsigned long long)(unsigned)(t + 1) << 32)
                   | (unsigned long long)__float_as_uint(an));
        }
        __syncthreads();   // protect smA before next stage overwrites it
    }

    if (blockIdx.x == 0 && tid == 0) g_csum = csum;
}

// Terminal: forward = LSE_j(A''(T)[j] + Wl[STOP,j]) + Csum (max-stabilized: the
// STOP row is uniformly -1e4, so without the max everything would underflow).
__global__ void crf_final(const float* __restrict__ trans, float* __restrict__ out)
{
    __shared__ float  sm[TPB];
    __shared__ double sd[TPB];
    int tid = threadIdx.x;

    float x[4];
    float m = -3.4e38f;
    #pragma unroll
    for (int q = 0; q < 4; ++q) {
        int jj = q * TPB + tid;
        float a  = __uint_as_float((unsigned)(g_pub[T_LEN & 1][jj] & 0xffffffffull));
        float wl = __ldg(&trans[(size_t)(L_LAB - 1) * L_LAB + jj]) * LOG2E;
        x[q] = a + wl;
        m = fmaxf(m, x[q]);
    }
    sm[tid] = m; __syncthreads();
    for (int s = TPB / 2; s > 0; s >>= 1) {
        if (tid < s) sm[tid] = fmaxf(sm[tid], sm[tid + s]);
        __syncthreads();
    }
    float M = sm[0];

    double loc = 0.0;
    #pragma unroll
    for (int q = 0; q < 4; ++q) loc += (double)ex2f(x[q] - M);
    sd[tid] = loc; __syncthreads();
    for (int s = TPB / 2; s > 0; s >>= 1) {
        if (tid < s) sd[tid] += sd[tid + s];
        __syncthreads();
    }
    if (tid == 0) {
        double fwd = (log2(sd[0]) + (double)M + g_csum) * LN2_D;
        out[0] = (float)(fwd - g_gold);
    }
}

extern "C" void kernel_launch(void* const* d_in, const int* in_sizes, int n_in,
                              void* d_out, int out_size)
{
    const float* pred = nullptr;
    const int*   ref  = nullptr;
    const float* trans = nullptr;
    for (int i = 0; i < n_in; ++i) {
        if (in_sizes[i] == T_LEN)                 ref   = (const int*)d_in[i];
        else if (in_sizes[i] == L_LAB * L_LAB)    trans = (const float*)d_in[i];
        else if (in_sizes[i] == T_LEN * L_LAB)    pred  = (const float*)d_in[i];
    }
    crf_reset<<<8, 256>>>();
    crf_main<<<NBLK + 1, TPB>>>(pred, ref, trans);
    crf_final<<<1, TPB>>>(trans, (float*)d_out);
}